// round 3
// baseline (speedup 1.0000x reference)
#include <cuda_runtime.h>
#include <cstdint>

#define N_NODES 50000
#define N_EDGES 800000
#define DIM     64
#define NLAYERS 3

// Scratch (no cudaMalloc allowed).
__device__ float  g_bufA[N_NODES * DIM];
__device__ float  g_bufB[N_NODES * DIM];
__device__ float  g_agg [N_NODES * DIM];
__device__ int    g_off [N_NODES + 1];
__device__ int    g_cur [N_NODES];      // running fill cursor (seeded with g_off)
__device__ float2 g_epk [N_EDGES];      // (.x = src index bits, .y = weight)

// ---------------------------------------------------------------------------
// CSR build (per call; reused by all 3 layers)
// ---------------------------------------------------------------------------
__global__ void csr_zero_kernel() {
    int i = blockIdx.x * blockDim.x + threadIdx.x;
    if (i < N_NODES / 4) ((int4*)g_cur)[i] = make_int4(0, 0, 0, 0);
}

// Histogram: 4 edges per thread (int4 load, 4 independent atomics -> MLP 4)
__global__ void csr_hist_kernel(const int4* __restrict__ dst4) {
    int q = blockIdx.x * blockDim.x + threadIdx.x;
    if (q >= N_EDGES / 4) return;
    int4 d = __ldg(dst4 + q);
    atomicAdd(&g_cur[d.x], 1);
    atomicAdd(&g_cur[d.y], 1);
    atomicAdd(&g_cur[d.z], 1);
    atomicAdd(&g_cur[d.w], 1);
}

// Single block, 1024 threads: exclusive scan g_cur -> g_off,
// and seed g_cur with the start offsets (fill cursor).
__global__ __launch_bounds__(1024) void csr_scan_kernel() {
    __shared__ int sums[1024];
    const int t  = threadIdx.x;
    const int CH = (N_NODES + 1023) / 1024;     // 49
    int lo = t * CH;
    int hi = lo + CH; if (hi > N_NODES) hi = N_NODES;
    if (lo > N_NODES) lo = N_NODES;

    int s = 0;
    for (int i = lo; i < hi; i++) s += g_cur[i];
    sums[t] = s;
    __syncthreads();
    #pragma unroll
    for (int off = 1; off < 1024; off <<= 1) {
        int v = (t >= off) ? sums[t - off] : 0;
        __syncthreads();
        sums[t] += v;
        __syncthreads();
    }
    int run = (t == 0) ? 0 : sums[t - 1];       // exclusive prefix
    for (int i = lo; i < hi; i++) {
        int c = g_cur[i];
        g_off[i] = run;
        g_cur[i] = run;                          // cursor = start offset
        run += c;
    }
    if (t == 1023) g_off[N_NODES] = run;        // == N_EDGES
}

// Fill: 4 edges per thread; single atomic per edge (cursor holds offsets).
__global__ void csr_fill_kernel(const int4*   __restrict__ src4,
                                const int4*   __restrict__ dst4,
                                const float4* __restrict__ ew4) {
    int q = blockIdx.x * blockDim.x + threadIdx.x;
    if (q >= N_EDGES / 4) return;
    int4   d = __ldg(dst4 + q);
    int4   s = __ldg(src4 + q);
    float4 w = __ldg(ew4  + q);
    int p0 = atomicAdd(&g_cur[d.x], 1);
    int p1 = atomicAdd(&g_cur[d.y], 1);
    int p2 = atomicAdd(&g_cur[d.z], 1);
    int p3 = atomicAdd(&g_cur[d.w], 1);
    g_epk[p0] = make_float2(__int_as_float(s.x), w.x);
    g_epk[p1] = make_float2(__int_as_float(s.y), w.y);
    g_epk[p2] = make_float2(__int_as_float(s.z), w.z);
    g_epk[p3] = make_float2(__int_as_float(s.w), w.w);
}

// ---------------------------------------------------------------------------
// Pull aggregation with batched edge keys + shuffle broadcast (MLP ~16).
// 16 threads per node, one float4 lane each. No atomics, no pre-zeroing.
// ---------------------------------------------------------------------------
__global__ __launch_bounds__(256) void pull_kernel(
    const float4* __restrict__ h,
    float4*       __restrict__ agg)
{
    int t = blockIdx.x * blockDim.x + threadIdx.x;
    int n = t >> 4;
    if (n >= N_NODES) return;
    const int      lane      = t & 15;
    const int      groupBase = threadIdx.x & 16;          // 0 or 16 within warp
    const unsigned groupMask = 0xFFFFu << groupBase;

    int beg = __ldg(g_off + n);
    int end = __ldg(g_off + n + 1);

    float4 acc = make_float4(0.f, 0.f, 0.f, 0.f);

    int j = beg;
    // Full batches of 16 edges: coalesced key load, 16 independent row loads.
    for (; j + 16 <= end; j += 16) {
        float2 ep = __ldg(g_epk + j + lane);
        #pragma unroll
        for (int k = 0; k < 16; k++) {
            int   s = __shfl_sync(groupMask, __float_as_int(ep.x), groupBase + k);
            float w = __shfl_sync(groupMask, ep.y, groupBase + k);
            float4 v = __ldg(h + (size_t)s * 16 + lane);
            acc.x += w * v.x; acc.y += w * v.y;
            acc.z += w * v.z; acc.w += w * v.w;
        }
    }
    // Tail: pad keys with w=0, process in chunks of 4 (<=3 wasted rows).
    if (j < end) {
        int jl = j + lane;
        float2 ep = (jl < end) ? __ldg(g_epk + jl)
                               : make_float2(0.f, 0.f);   // src=0, w=0 (harmless)
        int kn = end - j;                                  // 1..15
        for (int k = 0; k < kn; k += 4) {
            #pragma unroll
            for (int i = 0; i < 4; i++) {
                int   s = __shfl_sync(groupMask, __float_as_int(ep.x), groupBase + k + i);
                float w = __shfl_sync(groupMask, ep.y, groupBase + k + i);
                float4 v = __ldg(h + (size_t)s * 16 + lane);
                acc.x += w * v.x; acc.y += w * v.y;
                acc.z += w * v.z; acc.w += w * v.w;
            }
        }
    }
    agg[(size_t)n * 16 + lane] = acc;
}

// ---------------------------------------------------------------------------
// Fused dual GEMM: out = [H|AGG](K=128) @ [Wroot;Wrel] + bias (tanh optional)
// 256 threads, 64x64 tile, 4x4 per thread, W in SMEM.
// ---------------------------------------------------------------------------
__global__ __launch_bounds__(256) void gemm_kernel(
    const float* __restrict__ H,
    const float* __restrict__ AGG,
    const float* __restrict__ Wroot,   // [64][64]
    const float* __restrict__ Wrel,    // [64][64]
    const float* __restrict__ bias,    // [64]
    float*       __restrict__ out,
    int doTanh)
{
    __shared__ float Ws[128][64];   // k<64: Wroot, k>=64: Wrel
    __shared__ float As[16][68];    // [kk][row], padded

    const int tid = threadIdx.x;
    const int ty  = tid >> 4;
    const int tx  = tid & 15;
    const int rowBase = blockIdx.x * 64;

    #pragma unroll
    for (int it = 0; it < 8; it++) {
        int f4 = tid + it * 256;
        int k  = f4 >> 4;
        int jq = f4 & 15;
        const float* srcw = (k < 64) ? (Wroot + k * 64 + jq * 4)
                                     : (Wrel + (k - 64) * 64 + jq * 4);
        float4 wv = __ldg((const float4*)srcw);
        *(float4*)&Ws[k][jq * 4] = wv;
    }

    float acc[4][4];
    #pragma unroll
    for (int i = 0; i < 4; i++)
        #pragma unroll
        for (int j = 0; j < 4; j++) acc[i][j] = 0.f;

    const int ldRow   = tid >> 2;
    const int ldKpart = (tid & 3) * 4;
    const int gRow    = rowBase + ldRow;
    const bool rowOk  = (gRow < N_NODES);

    #pragma unroll 1
    for (int kc = 0; kc < 8; kc++) {
        __syncthreads();
        const float* srcA = (kc < 4) ? H : AGG;
        int kLocal = (kc & 3) * 16 + ldKpart;
        float4 av = make_float4(0.f, 0.f, 0.f, 0.f);
        if (rowOk) av = __ldg((const float4*)(srcA + (size_t)gRow * 64 + kLocal));
        As[ldKpart + 0][ldRow] = av.x;
        As[ldKpart + 1][ldRow] = av.y;
        As[ldKpart + 2][ldRow] = av.z;
        As[ldKpart + 3][ldRow] = av.w;
        __syncthreads();

        #pragma unroll
        for (int kk = 0; kk < 16; kk++) {
            float4 a = *(const float4*)&As[kk][ty * 4];
            float4 b = *(const float4*)&Ws[kc * 16 + kk][tx * 4];
            acc[0][0] += a.x * b.x; acc[0][1] += a.x * b.y;
            acc[0][2] += a.x * b.z; acc[0][3] += a.x * b.w;
            acc[1][0] += a.y * b.x; acc[1][1] += a.y * b.y;
            acc[1][2] += a.y * b.z; acc[1][3] += a.y * b.w;
            acc[2][0] += a.z * b.x; acc[2][1] += a.z * b.y;
            acc[2][2] += a.z * b.z; acc[2][3] += a.z * b.w;
            acc[3][0] += a.w * b.x; acc[3][1] += a.w * b.y;
            acc[3][2] += a.w * b.z; acc[3][3] += a.w * b.w;
        }
    }

    float4 bv = __ldg((const float4*)(bias + tx * 4));

    #pragma unroll
    for (int i = 0; i < 4; i++) {
        int r = rowBase + ty * 4 + i;
        if (r >= N_NODES) break;
        float4 o;
        o.x = acc[i][0] + bv.x;
        o.y = acc[i][1] + bv.y;
        o.z = acc[i][2] + bv.z;
        o.w = acc[i][3] + bv.w;
        if (doTanh) {
            o.x = tanhf(o.x); o.y = tanhf(o.y);
            o.z = tanhf(o.z); o.w = tanhf(o.w);
        }
        *(float4*)(out + (size_t)r * 64 + tx * 4) = o;
    }
}

// ---------------------------------------------------------------------------
// Launcher
// ---------------------------------------------------------------------------
extern "C" void kernel_launch(void* const* d_in, const int* in_sizes, int n_in,
                              void* d_out, int out_size)
{
    const float* x      = (const float*)d_in[0];   // [N, 64]
    const int*   eidx   = (const int*)  d_in[1];   // [2, E]
    const float* ew     = (const float*)d_in[2];   // [E]
    const float* W_rel  = (const float*)d_in[3];   // [L, 64, 64]
    const float* b_rel  = (const float*)d_in[4];   // [L, 64]
    const float* W_root = (const float*)d_in[5];   // [L, 64, 64]
    float* out = (float*)d_out;

    const int* src = eidx;            // row 0
    const int* dst = eidx + N_EDGES;  // row 1

    float *pA, *pB, *pAgg;
    cudaGetSymbolAddress((void**)&pA,   g_bufA);
    cudaGetSymbolAddress((void**)&pB,   g_bufB);
    cudaGetSymbolAddress((void**)&pAgg, g_agg);

    const int quadBlocks = (N_EDGES / 4 + 255) / 256;       // 782
    const int zeroBlocks = (N_NODES / 4 + 255) / 256;       // 49
    const int pullBlocks = (N_NODES * 16 + 255) / 256;      // 3125
    const int gemmBlocks = (N_NODES + 63) / 64;             // 782

    // Build CSR by dst (once per call; used by all layers).
    csr_zero_kernel<<<zeroBlocks, 256>>>();
    csr_hist_kernel<<<quadBlocks, 256>>>((const int4*)dst);
    csr_scan_kernel<<<1, 1024>>>();
    csr_fill_kernel<<<quadBlocks, 256>>>(
        (const int4*)src, (const int4*)dst, (const float4*)ew);

    const float* hprev = x;
    for (int layer = 0; layer < NLAYERS; layer++) {
        float* hnext = (layer == NLAYERS - 1) ? out : ((layer == 0) ? pA : pB);

        pull_kernel<<<pullBlocks, 256>>>((const float4*)hprev, (float4*)pAgg);
        gemm_kernel<<<gemmBlocks, 256>>>(
            hprev, pAgg,
            W_root + (size_t)layer * DIM * DIM,
            W_rel  + (size_t)layer * DIM * DIM,
            b_rel  + (size_t)layer * DIM,
            hnext,
            layer == NLAYERS - 1 ? 1 : 0);

        hprev = hnext;
    }
}

// round 4
// speedup vs baseline: 1.3606x; 1.3606x over previous
#include <cuda_runtime.h>
#include <cuda_bf16.h>
#include <cstdint>

#define N_NODES 50000
#define N_EDGES 800000
#define DIM     64
#define NLAYERS 3

// A/B row strides in bf16 elems (64 data + 8 pad -> conflict-free LDSM)
#define RA 72
#define RB 72
// SMEM offsets in bf16 elements
#define OFF_A_HI 0
#define OFF_A_LO (128 * RA)
#define OFF_B_HI (2 * 128 * RA)
#define OFF_B_LO (2 * 128 * RA + 64 * RB)
#define SMEM_ELEMS (2 * 128 * RA + 2 * 64 * RB)
#define SMEM_BYTES (SMEM_ELEMS * 2)

// Scratch (no cudaMalloc allowed).
__device__ float g_bufA[N_NODES * DIM];
__device__ float g_bufB[N_NODES * DIM];
__device__ float g_agg [N_NODES * DIM];

// ---------------------------------------------------------------------------
// Zero agg (once, before layer-1 scatter; later layers zeroed inside GEMM)
// ---------------------------------------------------------------------------
__global__ void zero_kernel(float4* __restrict__ p, int n4) {
    int i = blockIdx.x * blockDim.x + threadIdx.x;
    if (i < n4) p[i] = make_float4(0.f, 0.f, 0.f, 0.f);
}

// ---------------------------------------------------------------------------
// Push scatter: agg[dst] += ew * h[src]; 16 threads/edge, red.v4.f32.
// (At the LTS atomic-op floor; left as-is.)
// ---------------------------------------------------------------------------
__global__ __launch_bounds__(256) void scatter_kernel(
    const float4* __restrict__ h,
    const int*    __restrict__ src,
    const int*    __restrict__ dst,
    const float*  __restrict__ ew,
    float4*       __restrict__ agg)
{
    int t = blockIdx.x * blockDim.x + threadIdx.x;
    int e = t >> 4;
    if (e >= N_EDGES) return;
    int lane = t & 15;

    int   s = __ldg(src + e);
    int   d = __ldg(dst + e);
    float w = __ldg(ew  + e);

    float4 v = __ldg(h + (size_t)s * 16 + lane);
    float4* p = agg + (size_t)d * 16 + lane;
    asm volatile("red.global.add.v4.f32 [%0], {%1,%2,%3,%4};"
                 :: "l"(p), "f"(v.x * w), "f"(v.y * w), "f"(v.z * w), "f"(v.w * w)
                 : "memory");
}

// ---------------------------------------------------------------------------
// Tensor-core dual GEMM, bf16-split (hi/lo), fp32 accum:
//   out = H @ Wroot + AGG @ Wrel + bias   (tanh on last layer)
// Block: 256 thr (8 warps), tile 128 rows x 64 cols. Two K-stages share
// one accumulator. Warp tile 32x32 via mma.m16n8k16.
// ---------------------------------------------------------------------------
__device__ __forceinline__ void ldsm_x4(uint32_t& r0, uint32_t& r1,
                                        uint32_t& r2, uint32_t& r3,
                                        uint32_t addr) {
    asm volatile("ldmatrix.sync.aligned.m8n8.x4.shared.b16 {%0,%1,%2,%3}, [%4];"
                 : "=r"(r0), "=r"(r1), "=r"(r2), "=r"(r3) : "r"(addr));
}

__device__ __forceinline__ void mma_bf16(float* d, const uint32_t* a,
                                         uint32_t b0, uint32_t b1) {
    asm volatile(
        "mma.sync.aligned.m16n8k16.row.col.f32.bf16.bf16.f32 "
        "{%0,%1,%2,%3}, {%4,%5,%6,%7}, {%8,%9}, {%0,%1,%2,%3};"
        : "+f"(d[0]), "+f"(d[1]), "+f"(d[2]), "+f"(d[3])
        : "r"(a[0]), "r"(a[1]), "r"(a[2]), "r"(a[3]), "r"(b0), "r"(b1));
}

__device__ __forceinline__ void split2(float a, float b,
                                       __nv_bfloat162& h, __nv_bfloat162& l) {
    __nv_bfloat16 ha = __float2bfloat16_rn(a);
    __nv_bfloat16 hb = __float2bfloat16_rn(b);
    float la = a - __bfloat162float(ha);
    float lb = b - __bfloat162float(hb);
    h = __halves2bfloat162(ha, hb);
    l = __halves2bfloat162(__float2bfloat16_rn(la), __float2bfloat16_rn(lb));
}

__global__ __launch_bounds__(256) void gemm_tc_kernel(
    const float* __restrict__ H,
    float*                    AGG,     // no restrict: loaded then zeroed
    const float* __restrict__ Wroot,   // [64][64]
    const float* __restrict__ Wrel,    // [64][64]
    const float* __restrict__ bias,    // [64]
    float*       __restrict__ out,
    int doTanh, int doZero)
{
    extern __shared__ __nv_bfloat16 sm[];
    uint32_t sbase;
    asm("{.reg .u64 t; cvta.to.shared.u64 t, %1; cvt.u32.u64 %0, t;}"
        : "=r"(sbase) : "l"(sm));

    const int tid     = threadIdx.x;
    const int lane    = tid & 31;
    const int warp    = tid >> 5;
    const int wm      = warp >> 1;          // 0..3
    const int wn      = warp & 1;           // 0..1
    const int rowBase = blockIdx.x * 128;

    float acc[2][4][4];
    #pragma unroll
    for (int mi = 0; mi < 2; mi++)
        #pragma unroll
        for (int ni = 0; ni < 4; ni++)
            #pragma unroll
            for (int k = 0; k < 4; k++) acc[mi][ni][k] = 0.f;

    // LDSM source addresses (per warp, fixed across k-steps except k offset)
    const int m0 = wm * 32;
    const int n0 = wn * 32;
    const int aRow = m0 + (lane & 15);            // row within tile
    const int aColB = (lane >> 4) * 8;            // k sub-offset
    const int bRow = n0 + (lane & 7) + ((lane >> 4) * 8);
    const int bColB = ((lane >> 3) & 1) * 8;

    #pragma unroll 1
    for (int s = 0; s < 2; s++) {
        __syncthreads();   // previous stage's compute done before overwrite

        // ---- Stage A: 128 rows x 64 cols fp32 -> bf16 hi/lo in SMEM ----
        const float* S = s ? (const float*)AGG : H;
        #pragma unroll
        for (int i = 0; i < 8; i++) {
            int q   = tid + i * 256;        // 0..2047
            int row = q >> 4;               // 0..127
            int c4  = (q & 15) * 4;         // col 0..60 step 4
            int gr  = rowBase + row;
            float4 v = make_float4(0.f, 0.f, 0.f, 0.f);
            if (gr < N_NODES) v = *(const float4*)(S + (size_t)gr * 64 + c4);
            __nv_bfloat162 h0, l0, h1, l1;
            split2(v.x, v.y, h0, l0);
            split2(v.z, v.w, h1, l1);
            int base = row * RA + c4;
            *(__nv_bfloat162*)&sm[OFF_A_HI + base]     = h0;
            *(__nv_bfloat162*)&sm[OFF_A_HI + base + 2] = h1;
            *(__nv_bfloat162*)&sm[OFF_A_LO + base]     = l0;
            *(__nv_bfloat162*)&sm[OFF_A_LO + base + 2] = l1;
            if (s == 1 && doZero && gr < N_NODES)
                *(float4*)(AGG + (size_t)gr * 64 + c4) =
                    make_float4(0.f, 0.f, 0.f, 0.f);
        }

        // ---- Stage B: W^T (B[n][k] = W[k][n]) fp32 -> bf16 hi/lo ----
        const float* Wm = s ? Wrel : Wroot;
        #pragma unroll
        for (int i = 0; i < 16; i++) {
            int q = tid + i * 256;          // 0..4095
            int k = q >> 6;                 // 0..63
            int n = q & 63;
            float w = __ldg(Wm + k * 64 + n);
            __nv_bfloat16 hw = __float2bfloat16_rn(w);
            float lw = w - __bfloat162float(hw);
            sm[OFF_B_HI + n * RB + k] = hw;
            sm[OFF_B_LO + n * RB + k] = __float2bfloat16_rn(lw);
        }
        __syncthreads();

        // ---- Compute: 3 combos (hi*hi, hi*lo, lo*hi), K=64 each ----
        const int aOffC[3] = { OFF_A_HI, OFF_A_HI, OFF_A_LO };
        const int bOffC[3] = { OFF_B_HI, OFF_B_LO, OFF_B_HI };
        #pragma unroll
        for (int c = 0; c < 3; c++) {
            uint32_t aBase = sbase + (uint32_t)(aOffC[c] + aRow * RA + aColB) * 2;
            uint32_t bBase = sbase + (uint32_t)(bOffC[c] + bRow * RB + bColB) * 2;
            #pragma unroll
            for (int ks = 0; ks < 4; ks++) {
                uint32_t a[2][4], b[2][4];
                #pragma unroll
                for (int mi = 0; mi < 2; mi++)
                    ldsm_x4(a[mi][0], a[mi][1], a[mi][2], a[mi][3],
                            aBase + (uint32_t)(mi * 16 * RA + ks * 16) * 2);
                #pragma unroll
                for (int nb = 0; nb < 2; nb++)
                    ldsm_x4(b[nb][0], b[nb][1], b[nb][2], b[nb][3],
                            bBase + (uint32_t)(nb * 16 * RB + ks * 16) * 2);
                #pragma unroll
                for (int mi = 0; mi < 2; mi++)
                    #pragma unroll
                    for (int ni = 0; ni < 4; ni++)
                        mma_bf16(acc[mi][ni], a[mi],
                                 b[ni >> 1][(ni & 1) * 2],
                                 b[ni >> 1][(ni & 1) * 2 + 1]);
            }
        }
    }

    // ---- Epilogue: bias (+tanh), store fp32 ----
    #pragma unroll
    for (int mi = 0; mi < 2; mi++) {
        #pragma unroll
        for (int ni = 0; ni < 4; ni++) {
            int col = n0 + ni * 8 + (lane & 3) * 2;
            float b0 = __ldg(bias + col);
            float b1 = __ldg(bias + col + 1);
            int r0 = rowBase + m0 + mi * 16 + (lane >> 2);
            #pragma unroll
            for (int h = 0; h < 2; h++) {
                int r = r0 + h * 8;
                if (r >= N_NODES) continue;
                float v0 = acc[mi][ni][h * 2]     + b0;
                float v1 = acc[mi][ni][h * 2 + 1] + b1;
                if (doTanh) {
                    asm("tanh.approx.f32 %0, %0;" : "+f"(v0));
                    asm("tanh.approx.f32 %0, %0;" : "+f"(v1));
                }
                *(float2*)(out + (size_t)r * 64 + col) = make_float2(v0, v1);
            }
        }
    }
}

// ---------------------------------------------------------------------------
// Launcher
// ---------------------------------------------------------------------------
extern "C" void kernel_launch(void* const* d_in, const int* in_sizes, int n_in,
                              void* d_out, int out_size)
{
    const float* x      = (const float*)d_in[0];   // [N, 64]
    const int*   eidx   = (const int*)  d_in[1];   // [2, E]
    const float* ew     = (const float*)d_in[2];   // [E]
    const float* W_rel  = (const float*)d_in[3];   // [L, 64, 64]
    const float* b_rel  = (const float*)d_in[4];   // [L, 64]
    const float* W_root = (const float*)d_in[5];   // [L, 64, 64]
    float* out = (float*)d_out;

    const int* src = eidx;            // row 0
    const int* dst = eidx + N_EDGES;  // row 1

    float *pA, *pB, *pAgg;
    cudaGetSymbolAddress((void**)&pA,   g_bufA);
    cudaGetSymbolAddress((void**)&pB,   g_bufB);
    cudaGetSymbolAddress((void**)&pAgg, g_agg);

    static bool attrSet = false;
    if (!attrSet) {
        cudaFuncSetAttribute(gemm_tc_kernel,
                             cudaFuncAttributeMaxDynamicSharedMemorySize,
                             SMEM_BYTES);
        attrSet = true;
    }

    const int n4 = N_NODES * (DIM / 4);
    const int zeroBlocks    = (n4 + 255) / 256;
    const int scatterBlocks = (N_EDGES * 16 + 255) / 256;
    const int gemmBlocks    = (N_NODES + 127) / 128;   // 391

    // Launch order: zero, (scatter, gemm) x3 -> launch #6 = layer-3 scatter
    zero_kernel<<<zeroBlocks, 256>>>((float4*)pAgg, n4);

    const float* hprev = x;
    for (int layer = 0; layer < NLAYERS; layer++) {
        float* hnext = (layer == NLAYERS - 1) ? out : ((layer == 0) ? pA : pB);

        scatter_kernel<<<scatterBlocks, 256>>>(
            (const float4*)hprev, src, dst, ew, (float4*)pAgg);
        gemm_tc_kernel<<<gemmBlocks, 256, SMEM_BYTES>>>(
            hprev, pAgg,
            W_root + (size_t)layer * DIM * DIM,
            W_rel  + (size_t)layer * DIM * DIM,
            b_rel  + (size_t)layer * DIM,
            hnext,
            layer == NLAYERS - 1 ? 1 : 0,
            layer == NLAYERS - 1 ? 0 : 1);

        hprev = hnext;
    }
}

// round 5
// speedup vs baseline: 1.3816x; 1.0154x over previous
#include <cuda_runtime.h>
#include <cuda_bf16.h>
#include <cstdint>

#define N_NODES 50000
#define N_EDGES 800000
#define DIM     64
#define NLAYERS 3

// A/B row strides in bf16 elems (64 data + 8 pad -> conflict-free LDSM)
#define RA 72
#define RB 72
#define OFF_A_HI 0
#define OFF_A_LO (128 * RA)
#define OFF_B_HI (2 * 128 * RA)
#define OFF_B_LO (2 * 128 * RA + 64 * RB)
#define SMEM_ELEMS (2 * 128 * RA + 2 * 64 * RB)
#define SMEM_BYTES (SMEM_ELEMS * 2)

// Scratch (no cudaMalloc allowed).
__device__ float g_bufA[N_NODES * DIM];
__device__ float g_bufB[N_NODES * DIM];
__device__ float g_agg [N_NODES * DIM];

// ---------------------------------------------------------------------------
// Zero agg (once, before layer-1 scatter; later layers zeroed inside GEMM)
// ---------------------------------------------------------------------------
__global__ void zero_kernel(float4* __restrict__ p, int n4) {
    int i = blockIdx.x * blockDim.x + threadIdx.x;
    if (i < n4) p[i] = make_float4(0.f, 0.f, 0.f, 0.f);
}

// ---------------------------------------------------------------------------
// Scatter via TMA bulk-reduce: agg[dst] += ew * h[src].
// Each warp: 16 edges in 2 batches of 8. Stage w*h[src] rows (256B) in SMEM,
// then ONE thread per edge issues cp.reduce.async.bulk (L2-side f32 add).
// Replaces 16 REDG.128 lanes/edge of LSU issue with 1 bulk op/edge.
// 800000 edges = 50000 warps = 6250 blocks exactly (no guards needed).
// ---------------------------------------------------------------------------
__global__ __launch_bounds__(256) void scatter_tma_kernel(
    const float4* __restrict__ h,
    const int*    __restrict__ src,
    const int*    __restrict__ dst,
    const float*  __restrict__ ew,
    float*        __restrict__ agg)
{
    __shared__ float4 buf[8][2][8][16];   // [warp][batch][edge][lane16] = 32KB
    __shared__ int    dsts[8][2][8];

    const int warp = threadIdx.x >> 5;
    const int lane = threadIdx.x & 31;
    const int sub  = lane >> 4;            // 0/1: which edge of the pair
    const int l16  = lane & 15;

    const long warpGlobal = (long)blockIdx.x * 8 + warp;
    const long eBase      = warpGlobal * 16;

    #pragma unroll
    for (int b = 0; b < 2; b++) {
        // ---- Stage 8 edges (4 iters x 2 edges/warp) ----
        #pragma unroll
        for (int it = 0; it < 4; it++) {
            long e = eBase + b * 8 + it * 2 + sub;
            int s = 0, d = 0; float w = 0.f;
            if (l16 == 0) {                 // lanes 0 and 16 load edge keys
                s = __ldg(src + e);
                d = __ldg(dst + e);
                w = __ldg(ew  + e);
            }
            s = __shfl_sync(0xffffffffu, s, sub * 16);
            w = __shfl_sync(0xffffffffu, w, sub * 16);
            float4 v = __ldg(h + (size_t)s * 16 + l16);
            v.x *= w; v.y *= w; v.z *= w; v.w *= w;
            buf[warp][b][it * 2 + sub][l16] = v;
            if (l16 == 0) dsts[warp][b][it * 2 + sub] = d;
        }
        __syncwarp();
        asm volatile("fence.proxy.async.shared::cta;" ::: "memory");

        // ---- Issue 8 bulk reduces (one thread each) ----
        if (lane < 8) {
            int d = dsts[warp][b][lane];
            uint32_t sp = (uint32_t)__cvta_generic_to_shared(&buf[warp][b][lane][0]);
            float* gp = agg + (size_t)d * 64;
            asm volatile(
                "cp.reduce.async.bulk.global.shared::cta.bulk_group.add.f32 "
                "[%0], [%1], %2;"
                :: "l"(gp), "r"(sp), "n"(256) : "memory");
        }
        __syncwarp();
    }

    if (lane < 8) {
        asm volatile("cp.async.bulk.commit_group;" ::: "memory");
        asm volatile("cp.async.bulk.wait_group 0;" ::: "memory");
    }
}

// ---------------------------------------------------------------------------
// Tensor-core dual GEMM, bf16-split (hi/lo), fp32 accum (unchanged from R4).
// ---------------------------------------------------------------------------
__device__ __forceinline__ void ldsm_x4(uint32_t& r0, uint32_t& r1,
                                        uint32_t& r2, uint32_t& r3,
                                        uint32_t addr) {
    asm volatile("ldmatrix.sync.aligned.m8n8.x4.shared.b16 {%0,%1,%2,%3}, [%4];"
                 : "=r"(r0), "=r"(r1), "=r"(r2), "=r"(r3) : "r"(addr));
}

__device__ __forceinline__ void mma_bf16(float* d, const uint32_t* a,
                                         uint32_t b0, uint32_t b1) {
    asm volatile(
        "mma.sync.aligned.m16n8k16.row.col.f32.bf16.bf16.f32 "
        "{%0,%1,%2,%3}, {%4,%5,%6,%7}, {%8,%9}, {%0,%1,%2,%3};"
        : "+f"(d[0]), "+f"(d[1]), "+f"(d[2]), "+f"(d[3])
        : "r"(a[0]), "r"(a[1]), "r"(a[2]), "r"(a[3]), "r"(b0), "r"(b1));
}

__device__ __forceinline__ void split2(float a, float b,
                                       __nv_bfloat162& h, __nv_bfloat162& l) {
    __nv_bfloat16 ha = __float2bfloat16_rn(a);
    __nv_bfloat16 hb = __float2bfloat16_rn(b);
    float la = a - __bfloat162float(ha);
    float lb = b - __bfloat162float(hb);
    h = __halves2bfloat162(ha, hb);
    l = __halves2bfloat162(__float2bfloat16_rn(la), __float2bfloat16_rn(lb));
}

__global__ __launch_bounds__(256) void gemm_tc_kernel(
    const float* __restrict__ H,
    float*                    AGG,     // no restrict: loaded then zeroed
    const float* __restrict__ Wroot,   // [64][64]
    const float* __restrict__ Wrel,    // [64][64]
    const float* __restrict__ bias,    // [64]
    float*       __restrict__ out,
    int doTanh, int doZero)
{
    extern __shared__ __nv_bfloat16 sm[];
    uint32_t sbase;
    asm("{.reg .u64 t; cvta.to.shared.u64 t, %1; cvt.u32.u64 %0, t;}"
        : "=r"(sbase) : "l"(sm));

    const int tid     = threadIdx.x;
    const int lane    = tid & 31;
    const int warp    = tid >> 5;
    const int wm      = warp >> 1;
    const int wn      = warp & 1;
    const int rowBase = blockIdx.x * 128;

    float acc[2][4][4];
    #pragma unroll
    for (int mi = 0; mi < 2; mi++)
        #pragma unroll
        for (int ni = 0; ni < 4; ni++)
            #pragma unroll
            for (int k = 0; k < 4; k++) acc[mi][ni][k] = 0.f;

    const int m0 = wm * 32;
    const int n0 = wn * 32;
    const int aRow = m0 + (lane & 15);
    const int aColB = (lane >> 4) * 8;
    const int bRow = n0 + (lane & 7) + ((lane >> 4) * 8);
    const int bColB = ((lane >> 3) & 1) * 8;

    #pragma unroll 1
    for (int s = 0; s < 2; s++) {
        __syncthreads();

        const float* S = s ? (const float*)AGG : H;
        #pragma unroll
        for (int i = 0; i < 8; i++) {
            int q   = tid + i * 256;
            int row = q >> 4;
            int c4  = (q & 15) * 4;
            int gr  = rowBase + row;
            float4 v = make_float4(0.f, 0.f, 0.f, 0.f);
            if (gr < N_NODES) v = *(const float4*)(S + (size_t)gr * 64 + c4);
            __nv_bfloat162 h0, l0, h1, l1;
            split2(v.x, v.y, h0, l0);
            split2(v.z, v.w, h1, l1);
            int base = row * RA + c4;
            *(__nv_bfloat162*)&sm[OFF_A_HI + base]     = h0;
            *(__nv_bfloat162*)&sm[OFF_A_HI + base + 2] = h1;
            *(__nv_bfloat162*)&sm[OFF_A_LO + base]     = l0;
            *(__nv_bfloat162*)&sm[OFF_A_LO + base + 2] = l1;
            if (s == 1 && doZero && gr < N_NODES)
                *(float4*)(AGG + (size_t)gr * 64 + c4) =
                    make_float4(0.f, 0.f, 0.f, 0.f);
        }

        const float* Wm = s ? Wrel : Wroot;
        #pragma unroll
        for (int i = 0; i < 16; i++) {
            int q = tid + i * 256;
            int k = q >> 6;
            int n = q & 63;
            float w = __ldg(Wm + k * 64 + n);
            __nv_bfloat16 hw = __float2bfloat16_rn(w);
            float lw = w - __bfloat162float(hw);
            sm[OFF_B_HI + n * RB + k] = hw;
            sm[OFF_B_LO + n * RB + k] = __float2bfloat16_rn(lw);
        }
        __syncthreads();

        const int aOffC[3] = { OFF_A_HI, OFF_A_HI, OFF_A_LO };
        const int bOffC[3] = { OFF_B_HI, OFF_B_LO, OFF_B_HI };
        #pragma unroll
        for (int c = 0; c < 3; c++) {
            uint32_t aBase = sbase + (uint32_t)(aOffC[c] + aRow * RA + aColB) * 2;
            uint32_t bBase = sbase + (uint32_t)(bOffC[c] + bRow * RB + bColB) * 2;
            #pragma unroll
            for (int ks = 0; ks < 4; ks++) {
                uint32_t a[2][4], b[2][4];
                #pragma unroll
                for (int mi = 0; mi < 2; mi++)
                    ldsm_x4(a[mi][0], a[mi][1], a[mi][2], a[mi][3],
                            aBase + (uint32_t)(mi * 16 * RA + ks * 16) * 2);
                #pragma unroll
                for (int nb = 0; nb < 2; nb++)
                    ldsm_x4(b[nb][0], b[nb][1], b[nb][2], b[nb][3],
                            bBase + (uint32_t)(nb * 16 * RB + ks * 16) * 2);
                #pragma unroll
                for (int mi = 0; mi < 2; mi++)
                    #pragma unroll
                    for (int ni = 0; ni < 4; ni++)
                        mma_bf16(acc[mi][ni], a[mi],
                                 b[ni >> 1][(ni & 1) * 2],
                                 b[ni >> 1][(ni & 1) * 2 + 1]);
            }
        }
    }

    #pragma unroll
    for (int mi = 0; mi < 2; mi++) {
        #pragma unroll
        for (int ni = 0; ni < 4; ni++) {
            int col = n0 + ni * 8 + (lane & 3) * 2;
            float b0 = __ldg(bias + col);
            float b1 = __ldg(bias + col + 1);
            int r0 = rowBase + m0 + mi * 16 + (lane >> 2);
            #pragma unroll
            for (int h = 0; h < 2; h++) {
                int r = r0 + h * 8;
                if (r >= N_NODES) continue;
                float v0 = acc[mi][ni][h * 2]     + b0;
                float v1 = acc[mi][ni][h * 2 + 1] + b1;
                if (doTanh) {
                    asm("tanh.approx.f32 %0, %0;" : "+f"(v0));
                    asm("tanh.approx.f32 %0, %0;" : "+f"(v1));
                }
                *(float2*)(out + (size_t)r * 64 + col) = make_float2(v0, v1);
            }
        }
    }
}

// ---------------------------------------------------------------------------
// Launcher
// ---------------------------------------------------------------------------
extern "C" void kernel_launch(void* const* d_in, const int* in_sizes, int n_in,
                              void* d_out, int out_size)
{
    const float* x      = (const float*)d_in[0];   // [N, 64]
    const int*   eidx   = (const int*)  d_in[1];   // [2, E]
    const float* ew     = (const float*)d_in[2];   // [E]
    const float* W_rel  = (const float*)d_in[3];   // [L, 64, 64]
    const float* b_rel  = (const float*)d_in[4];   // [L, 64]
    const float* W_root = (const float*)d_in[5];   // [L, 64, 64]
    float* out = (float*)d_out;

    const int* src = eidx;            // row 0
    const int* dst = eidx + N_EDGES;  // row 1

    float *pA, *pB, *pAgg;
    cudaGetSymbolAddress((void**)&pA,   g_bufA);
    cudaGetSymbolAddress((void**)&pB,   g_bufB);
    cudaGetSymbolAddress((void**)&pAgg, g_agg);

    static bool attrSet = false;
    if (!attrSet) {
        cudaFuncSetAttribute(gemm_tc_kernel,
                             cudaFuncAttributeMaxDynamicSharedMemorySize,
                             SMEM_BYTES);
        attrSet = true;
    }

    const int n4 = N_NODES * (DIM / 4);
    const int zeroBlocks    = (n4 + 255) / 256;
    const int scatterBlocks = N_EDGES / (8 * 16);      // 6250, exact
    const int gemmBlocks    = (N_NODES + 127) / 128;   // 391

    // Launch order: zero, (scatter, gemm) x3 -> launch #6 = layer-3 scatter
    zero_kernel<<<zeroBlocks, 256>>>((float4*)pAgg, n4);

    const float* hprev = x;
    for (int layer = 0; layer < NLAYERS; layer++) {
        float* hnext = (layer == NLAYERS - 1) ? out : ((layer == 0) ? pA : pB);

        scatter_tma_kernel<<<scatterBlocks, 256>>>(
            (const float4*)hprev, src, dst, ew, pAgg);
        gemm_tc_kernel<<<gemmBlocks, 256, SMEM_BYTES>>>(
            hprev, pAgg,
            W_root + (size_t)layer * DIM * DIM,
            W_rel  + (size_t)layer * DIM * DIM,
            b_rel  + (size_t)layer * DIM,
            hnext,
            layer == NLAYERS - 1 ? 1 : 0,
            layer == NLAYERS - 1 ? 0 : 1);

        hprev = hnext;
    }
}

// round 6
// speedup vs baseline: 1.4346x; 1.0384x over previous
#include <cuda_runtime.h>
#include <cuda_bf16.h>
#include <cstdint>

#define N_NODES 50000
#define N_EDGES 800000
#define DIM     64
#define NLAYERS 3

// A/B row strides in bf16 elems (64 data + 8 pad -> conflict-free LDSM)
#define RA 72
#define RB 72
#define OFF_A_HI 0
#define OFF_A_LO (128 * RA)
#define OFF_B_HI (2 * 128 * RA)
#define OFF_B_LO (2 * 128 * RA + 64 * RB)
#define SMEM_ELEMS (2 * 128 * RA + 2 * 64 * RB)
#define SMEM_BYTES (SMEM_ELEMS * 2)

// Scratch (no cudaMalloc allowed).
__device__ float g_bufA[N_NODES * DIM];
__device__ float g_bufB[N_NODES * DIM];
__device__ float g_agg [N_NODES * DIM];

// ---------------------------------------------------------------------------
// Zero agg (once, before layer-1 scatter; later layers zeroed inside GEMM)
// ---------------------------------------------------------------------------
__global__ void zero_kernel(float4* __restrict__ p, int n4) {
    int i = blockIdx.x * blockDim.x + threadIdx.x;
    if (i < n4) p[i] = make_float4(0.f, 0.f, 0.f, 0.f);
}

// ---------------------------------------------------------------------------
// Scatter via TMA bulk-reduce: agg[dst] += ew * h[src].
// Per warp: 16 edges. Lane<16 owns edge 'lane' keys (coalesced LDGs);
// stage loop broadcasts (src,w) by shuffle, 2 edges/iter, 8 independent
// gathers in flight; ONE fence; lane<16 issues its own bulk reduce with
// its own dst (no SMEM key traffic).
// 128 thr/block (4 warps, 16KB buf) -> ~13 CTAs/SM for latency cover.
// 800000 edges = 50000 warps = 12500 blocks exactly.
// ---------------------------------------------------------------------------
__global__ __launch_bounds__(128) void scatter_tma_kernel(
    const float4* __restrict__ h,
    const int*    __restrict__ src,
    const int*    __restrict__ dst,
    const float*  __restrict__ ew,
    float*        __restrict__ agg)
{
    __shared__ float4 buf[4][16][16];   // [warp][edge][lane16] = 16KB

    const int warp = threadIdx.x >> 5;
    const int lane = threadIdx.x & 31;
    const int sub  = lane >> 4;            // which edge of the pair
    const int l16  = lane & 15;

    const long eBase = ((long)blockIdx.x * 4 + warp) * 16;

    // Coalesced key loads: lane i (i<16) owns edge eBase+i.
    int   myS = 0, myD = 0;
    float myW = 0.f;
    if (lane < 16) {
        myS = __ldg(src + eBase + lane);
        myD = __ldg(dst + eBase + lane);
        myW = __ldg(ew  + eBase + lane);
    }

    // Stage 16 weighted rows (2 edges per iteration, 8 gathers in flight).
    #pragma unroll
    for (int it = 0; it < 8; it++) {
        int   k = it * 2 + sub;
        int   s = __shfl_sync(0xffffffffu, myS, k);
        float w = __shfl_sync(0xffffffffu, myW, k);
        float4 v = __ldg(h + (size_t)s * 16 + l16);
        v.x *= w; v.y *= w; v.z *= w; v.w *= w;
        buf[warp][k][l16] = v;
    }
    __syncwarp();
    asm volatile("fence.proxy.async.shared::cta;" ::: "memory");

    // One bulk reduce per edge, issued by the owning lane.
    if (lane < 16) {
        uint32_t sp = (uint32_t)__cvta_generic_to_shared(&buf[warp][lane][0]);
        float* gp = agg + (size_t)myD * 64;
        asm volatile(
            "cp.reduce.async.bulk.global.shared::cta.bulk_group.add.f32 "
            "[%0], [%1], %2;"
            :: "l"(gp), "r"(sp), "n"(256) : "memory");
        asm volatile("cp.async.bulk.commit_group;" ::: "memory");
        asm volatile("cp.async.bulk.wait_group 0;" ::: "memory");
    }
}

// ---------------------------------------------------------------------------
// Tensor-core dual GEMM, bf16-split (hi/lo), fp32 accum (unchanged):
//   out = H @ Wroot + AGG @ Wrel + bias   (tanh on last layer)
// ---------------------------------------------------------------------------
__device__ __forceinline__ void ldsm_x4(uint32_t& r0, uint32_t& r1,
                                        uint32_t& r2, uint32_t& r3,
                                        uint32_t addr) {
    asm volatile("ldmatrix.sync.aligned.m8n8.x4.shared.b16 {%0,%1,%2,%3}, [%4];"
                 : "=r"(r0), "=r"(r1), "=r"(r2), "=r"(r3) : "r"(addr));
}

__device__ __forceinline__ void mma_bf16(float* d, const uint32_t* a,
                                         uint32_t b0, uint32_t b1) {
    asm volatile(
        "mma.sync.aligned.m16n8k16.row.col.f32.bf16.bf16.f32 "
        "{%0,%1,%2,%3}, {%4,%5,%6,%7}, {%8,%9}, {%0,%1,%2,%3};"
        : "+f"(d[0]), "+f"(d[1]), "+f"(d[2]), "+f"(d[3])
        : "r"(a[0]), "r"(a[1]), "r"(a[2]), "r"(a[3]), "r"(b0), "r"(b1));
}

__device__ __forceinline__ void split2(float a, float b,
                                       __nv_bfloat162& h, __nv_bfloat162& l) {
    __nv_bfloat16 ha = __float2bfloat16_rn(a);
    __nv_bfloat16 hb = __float2bfloat16_rn(b);
    float la = a - __bfloat162float(ha);
    float lb = b - __bfloat162float(hb);
    h = __halves2bfloat162(ha, hb);
    l = __halves2bfloat162(__float2bfloat16_rn(la), __float2bfloat16_rn(lb));
}

__global__ __launch_bounds__(256) void gemm_tc_kernel(
    const float* __restrict__ H,
    float*                    AGG,     // no restrict: loaded then zeroed
    const float* __restrict__ Wroot,   // [64][64]
    const float* __restrict__ Wrel,    // [64][64]
    const float* __restrict__ bias,    // [64]
    float*       __restrict__ out,
    int doTanh, int doZero)
{
    extern __shared__ __nv_bfloat16 sm[];
    uint32_t sbase;
    asm("{.reg .u64 t; cvta.to.shared.u64 t, %1; cvt.u32.u64 %0, t;}"
        : "=r"(sbase) : "l"(sm));

    const int tid     = threadIdx.x;
    const int lane    = tid & 31;
    const int warp    = tid >> 5;
    const int wm      = warp >> 1;
    const int wn      = warp & 1;
    const int rowBase = blockIdx.x * 128;

    float acc[2][4][4];
    #pragma unroll
    for (int mi = 0; mi < 2; mi++)
        #pragma unroll
        for (int ni = 0; ni < 4; ni++)
            #pragma unroll
            for (int k = 0; k < 4; k++) acc[mi][ni][k] = 0.f;

    const int m0 = wm * 32;
    const int n0 = wn * 32;
    const int aRow = m0 + (lane & 15);
    const int aColB = (lane >> 4) * 8;
    const int bRow = n0 + (lane & 7) + ((lane >> 4) * 8);
    const int bColB = ((lane >> 3) & 1) * 8;

    #pragma unroll 1
    for (int s = 0; s < 2; s++) {
        __syncthreads();

        const float* S = s ? (const float*)AGG : H;
        #pragma unroll
        for (int i = 0; i < 8; i++) {
            int q   = tid + i * 256;
            int row = q >> 4;
            int c4  = (q & 15) * 4;
            int gr  = rowBase + row;
            float4 v = make_float4(0.f, 0.f, 0.f, 0.f);
            if (gr < N_NODES) v = *(const float4*)(S + (size_t)gr * 64 + c4);
            __nv_bfloat162 h0, l0, h1, l1;
            split2(v.x, v.y, h0, l0);
            split2(v.z, v.w, h1, l1);
            int base = row * RA + c4;
            *(__nv_bfloat162*)&sm[OFF_A_HI + base]     = h0;
            *(__nv_bfloat162*)&sm[OFF_A_HI + base + 2] = h1;
            *(__nv_bfloat162*)&sm[OFF_A_LO + base]     = l0;
            *(__nv_bfloat162*)&sm[OFF_A_LO + base + 2] = l1;
            if (s == 1 && doZero && gr < N_NODES)
                *(float4*)(AGG + (size_t)gr * 64 + c4) =
                    make_float4(0.f, 0.f, 0.f, 0.f);
        }

        const float* Wm = s ? Wrel : Wroot;
        #pragma unroll
        for (int i = 0; i < 16; i++) {
            int q = tid + i * 256;
            int k = q >> 6;
            int n = q & 63;
            float w = __ldg(Wm + k * 64 + n);
            __nv_bfloat16 hw = __float2bfloat16_rn(w);
            float lw = w - __bfloat162float(hw);
            sm[OFF_B_HI + n * RB + k] = hw;
            sm[OFF_B_LO + n * RB + k] = __float2bfloat16_rn(lw);
        }
        __syncthreads();

        const int aOffC[3] = { OFF_A_HI, OFF_A_HI, OFF_A_LO };
        const int bOffC[3] = { OFF_B_HI, OFF_B_LO, OFF_B_HI };
        #pragma unroll
        for (int c = 0; c < 3; c++) {
            uint32_t aBase = sbase + (uint32_t)(aOffC[c] + aRow * RA + aColB) * 2;
            uint32_t bBase = sbase + (uint32_t)(bOffC[c] + bRow * RB + bColB) * 2;
            #pragma unroll
            for (int ks = 0; ks < 4; ks++) {
                uint32_t a[2][4], b[2][4];
                #pragma unroll
                for (int mi = 0; mi < 2; mi++)
                    ldsm_x4(a[mi][0], a[mi][1], a[mi][2], a[mi][3],
                            aBase + (uint32_t)(mi * 16 * RA + ks * 16) * 2);
                #pragma unroll
                for (int nb = 0; nb < 2; nb++)
                    ldsm_x4(b[nb][0], b[nb][1], b[nb][2], b[nb][3],
                            bBase + (uint32_t)(nb * 16 * RB + ks * 16) * 2);
                #pragma unroll
                for (int mi = 0; mi < 2; mi++)
                    #pragma unroll
                    for (int ni = 0; ni < 4; ni++)
                        mma_bf16(acc[mi][ni], a[mi],
                                 b[ni >> 1][(ni & 1) * 2],
                                 b[ni >> 1][(ni & 1) * 2 + 1]);
            }
        }
    }

    #pragma unroll
    for (int mi = 0; mi < 2; mi++) {
        #pragma unroll
        for (int ni = 0; ni < 4; ni++) {
            int col = n0 + ni * 8 + (lane & 3) * 2;
            float b0 = __ldg(bias + col);
            float b1 = __ldg(bias + col + 1);
            int r0 = rowBase + m0 + mi * 16 + (lane >> 2);
            #pragma unroll
            for (int h = 0; h < 2; h++) {
                int r = r0 + h * 8;
                if (r >= N_NODES) continue;
                float v0 = acc[mi][ni][h * 2]     + b0;
                float v1 = acc[mi][ni][h * 2 + 1] + b1;
                if (doTanh) {
                    asm("tanh.approx.f32 %0, %0;" : "+f"(v0));
                    asm("tanh.approx.f32 %0, %0;" : "+f"(v1));
                }
                *(float2*)(out + (size_t)r * 64 + col) = make_float2(v0, v1);
            }
        }
    }
}

// ---------------------------------------------------------------------------
// Launcher
// ---------------------------------------------------------------------------
extern "C" void kernel_launch(void* const* d_in, const int* in_sizes, int n_in,
                              void* d_out, int out_size)
{
    const float* x      = (const float*)d_in[0];   // [N, 64]
    const int*   eidx   = (const int*)  d_in[1];   // [2, E]
    const float* ew     = (const float*)d_in[2];   // [E]
    const float* W_rel  = (const float*)d_in[3];   // [L, 64, 64]
    const float* b_rel  = (const float*)d_in[4];   // [L, 64]
    const float* W_root = (const float*)d_in[5];   // [L, 64, 64]
    float* out = (float*)d_out;

    const int* src = eidx;            // row 0
    const int* dst = eidx + N_EDGES;  // row 1

    float *pA, *pB, *pAgg;
    cudaGetSymbolAddress((void**)&pA,   g_bufA);
    cudaGetSymbolAddress((void**)&pB,   g_bufB);
    cudaGetSymbolAddress((void**)&pAgg, g_agg);

    static bool attrSet = false;
    if (!attrSet) {
        cudaFuncSetAttribute(gemm_tc_kernel,
                             cudaFuncAttributeMaxDynamicSharedMemorySize,
                             SMEM_BYTES);
        attrSet = true;
    }

    const int n4 = N_NODES * (DIM / 4);
    const int zeroBlocks    = (n4 + 255) / 256;
    const int scatterBlocks = N_EDGES / (4 * 16);      // 12500, exact
    const int gemmBlocks    = (N_NODES + 127) / 128;   // 391

    // Launch order: zero, (scatter, gemm) x3 -> launch #6 = layer-3 scatter
    zero_kernel<<<zeroBlocks, 256>>>((float4*)pAgg, n4);

    const float* hprev = x;
    for (int layer = 0; layer < NLAYERS; layer++) {
        float* hnext = (layer == NLAYERS - 1) ? out : ((layer == 0) ? pA : pB);

        scatter_tma_kernel<<<scatterBlocks, 128>>>(
            (const float4*)hprev, src, dst, ew, pAgg);
        gemm_tc_kernel<<<gemmBlocks, 256, SMEM_BYTES>>>(
            hprev, pAgg,
            W_root + (size_t)layer * DIM * DIM,
            W_rel  + (size_t)layer * DIM * DIM,
            b_rel  + (size_t)layer * DIM,
            hnext,
            layer == NLAYERS - 1 ? 1 : 0,
            layer == NLAYERS - 1 ? 0 : 1);

        hprev = hnext;
    }
}